// round 7
// baseline (speedup 1.0000x reference)
#include <cuda_runtime.h>
#include <cuda_bf16.h>
#include <cstdint>

#define MSL 256
#define EMB 1024
#define NHID 64
#define NSLAB 8
#define DSLAB (EMB / NSLAB)   // 128
#define NEGF (-1e20f)

// Transposed scratch for coalesced reduction: [in/mem][slab][k][pos]
__device__ float g_part[2][NSLAB][NHID][MSL];
// Reduced + ReLU'd hidden vectors. [in/mem][k]
__device__ float g_h[2][NHID];

// ---------------------------------------------------------------------------
// Kernel A: fused dual GEMV over w1, K-split for full occupancy.
// grid = 2048 (pos = b>>3, slab = b&7), block = 256 threads, 32 regs.
// 8 blocks/SM x 256 thr = 64 warps/SM (full). Each block streams its
// contiguous 32KB w1 slab once: 8 fully-unrolled independent float4 loads
// per thread, coalesced across the block. Plain LDG only (no async-copy —
// that path is implicated in the R5/R6 container failures).
// ---------------------------------------------------------------------------
__global__ __launch_bounds__(256) void gemv_kernel(
    const int* __restrict__ toks_in, int n_toks,
    const int* __restrict__ toks_mem,
    const float* __restrict__ emb,
    const float* __restrict__ w1)
{
    __shared__ float s_in[DSLAB];
    __shared__ float s_mem[DSLAB];
    __shared__ float red_in[16][NHID];
    __shared__ float red_mem[16][NHID];

    const int pos    = blockIdx.x >> 3;
    const int slab   = blockIdx.x & 7;
    const int d_base = slab * DSLAB;
    const int t      = threadIdx.x;

    const int tok_in  = (pos < n_toks) ? toks_in[pos] : 0;  // PAD = 0
    const int tok_mem = toks_mem[pos];

    // Stage the two 512B embedding slab segments into SMEM.
    if (t < 32) {
        ((float4*)s_in)[t] =
            ((const float4*)(emb + (size_t)tok_in * EMB + d_base))[t];
    } else if (t < 64) {
        ((float4*)s_mem)[t - 32] =
            ((const float4*)(emb + (size_t)tok_mem * EMB + d_base))[t - 32];
    }
    __syncthreads();

    const float4* wrow4 =
        (const float4*)(w1 + ((size_t)pos * EMB + d_base) * NHID);
    const int j_off = t >> 4;          // 0..15  (d stripe)
    const int k0    = (t & 15) * 4;    // 0,4,...,60

    float4 ai = make_float4(0.f, 0.f, 0.f, 0.f);
    float4 am = make_float4(0.f, 0.f, 0.f, 0.f);

    #pragma unroll
    for (int d0 = 0; d0 < DSLAB; d0 += 16) {
        float4 w = wrow4[d0 * 16 + t];   // contiguous 4KB across the block
        int   d  = d0 + j_off;
        float a  = s_in[d];
        float b  = s_mem[d];
        ai.x += a * w.x; ai.y += a * w.y; ai.z += a * w.z; ai.w += a * w.w;
        am.x += b * w.x; am.y += b * w.y; am.z += b * w.z; am.w += b * w.w;
    }

    red_in [j_off][k0 + 0] = ai.x;
    red_in [j_off][k0 + 1] = ai.y;
    red_in [j_off][k0 + 2] = ai.z;
    red_in [j_off][k0 + 3] = ai.w;
    red_mem[j_off][k0 + 0] = am.x;
    red_mem[j_off][k0 + 1] = am.y;
    red_mem[j_off][k0 + 2] = am.z;
    red_mem[j_off][k0 + 3] = am.w;
    __syncthreads();

    if (t < NHID) {
        float si = 0.f, sm = 0.f;
        #pragma unroll
        for (int r = 0; r < 16; ++r) {
            si += red_in [r][t];
            sm += red_mem[r][t];
        }
        g_part[0][slab][t][pos] = si;
        g_part[1][slab][t][pos] = sm;
    }
}

// ---------------------------------------------------------------------------
// Kernel B: reduce g_part over (slab, pos) -> +b1 -> ReLU -> g_h.
// grid = 128 (one block per (s,k)), block = 256 (one thread per pos).
// Loads fully coalesced thanks to the [k][pos] scratch layout.
// ---------------------------------------------------------------------------
__global__ __launch_bounds__(256) void reduce_kernel(
    const float* __restrict__ b1)
{
    __shared__ float warp_sums[8];
    const int s = blockIdx.x >> 6;     // 0..1
    const int k = blockIdx.x & 63;     // 0..63
    const int t = threadIdx.x;

    float v = 0.f;
    #pragma unroll
    for (int sl = 0; sl < NSLAB; ++sl)
        v += g_part[s][sl][k][t];

    #pragma unroll
    for (int off = 16; off > 0; off >>= 1)
        v += __shfl_down_sync(0xffffffffu, v, off);
    if ((t & 31) == 0) warp_sums[t >> 5] = v;
    __syncthreads();
    if (t == 0) {
        float sum = 0.f;
        #pragma unroll
        for (int w = 0; w < 8; ++w) sum += warp_sums[w];
        g_h[s][k] = fmaxf(sum + b1[k], 0.f);
    }
}

// ---------------------------------------------------------------------------
// Bitonic sort of 512 u64 keys in shared memory, 256 threads, ascending.
// j <= 32 stages stay inside warp-private 64-element segments -> __syncwarp.
// ---------------------------------------------------------------------------
__device__ __forceinline__ void bitonic_sort_512(unsigned long long* keys)
{
    const int t = threadIdx.x;
    bool prev_cross = true;
    for (int k = 2; k <= 512; k <<= 1) {
        for (int j = k >> 1; j > 0; j >>= 1) {
            const bool cross = (j >= 64);
            if (cross || prev_cross) __syncthreads();
            else                     __syncwarp();
            prev_cross = cross;
            int i   = ((t & ~(j - 1)) << 1) | (t & (j - 1));
            int ixj = i | j;
            unsigned long long a = keys[i];
            unsigned long long b = keys[ixj];
            bool up = ((i & k) == 0);
            if ((a > b) == up) { keys[i] = b; keys[ixj] = a; }
        }
    }
    __syncthreads();
}

// ---------------------------------------------------------------------------
// Kernel C: layer2 + sigmoid -> mask PAD -> scatter-max dedup + top-k via
// two bitonic sorts -> emit. 1 block, 256 threads.
// ---------------------------------------------------------------------------
__global__ __launch_bounds__(256) void final_kernel(
    const int* __restrict__ toks_in, int n_toks,
    const int* __restrict__ toks_mem,
    const float* __restrict__ w2,
    const float* __restrict__ b2,
    float* __restrict__ out)
{
    __shared__ float h_in[NHID];
    __shared__ float h_mem[NHID];
    __shared__ unsigned long long keys[512];

    const int t = threadIdx.x;

    // Kick off token loads early.
    int tok_a = (t < n_toks) ? toks_in[t] : 0;
    int tok_b = toks_mem[t];

    if (t < NHID)        h_in [t]        = g_h[0][t];
    else if (t < 2*NHID) h_mem[t - NHID] = g_h[1][t - NHID];
    __syncthreads();

    // ---- layer 2 + sigmoid (w2 column shared by both score vectors) ----
    float si, sm;
    {
        si = b2[t];
        sm = si;
        #pragma unroll 16
        for (int k = 0; k < NHID; ++k) {
            float w = w2[k * MSL + t];   // coalesced over t
            si += h_in[k]  * w;
            sm += h_mem[k] * w;
        }
        si = 1.f / (1.f + expf(-si));
        sm = 1.f / (1.f + expf(-sm));
    }

    // ---- build keys (token asc, score desc); PAD -> sentinel ----
    {
        unsigned sb_a = __float_as_uint(si);   // positive floats: bits monotonic
        unsigned sb_b = __float_as_uint(sm);
        keys[t] = (tok_a == 0) ? ~0ull
                 : (((unsigned long long)(unsigned)tok_a << 32) | (unsigned)(~sb_a));
        keys[t + 256] = (tok_b == 0) ? ~0ull
                 : (((unsigned long long)(unsigned)tok_b << 32) | (unsigned)(~sb_b));
    }

    // Sort1: groups duplicates; best score first within each token group.
    bitonic_sort_512(keys);

    // ---- dedup (scatter-max): winner = first entry of its token ----
    unsigned long long k_a = keys[t];
    unsigned long long k_b = keys[t + 256];
    unsigned long long p_a = (t == 0) ? ~0ull : keys[t - 1];
    unsigned long long p_b = keys[t + 255];
    bool win_a = (k_a != ~0ull) && (t == 0 || (k_a >> 32) != (p_a >> 32));
    bool win_b = (k_b != ~0ull) && ((k_b >> 32) != (p_b >> 32));
    __syncthreads();

    // key2 = swap halves: (~score_bits)<<32 | token -> asc = score desc, tok asc
    keys[t]       = win_a ? ((k_a << 32) | (k_a >> 32)) : ~0ull;
    keys[t + 256] = win_b ? ((k_b << 32) | (k_b >> 32)) : ~0ull;

    // Sort2: top-k order.
    bitonic_sort_512(keys);

    // ---- emit first 256 (tokens as float, then scores) ----
    {
        unsigned long long r = keys[t];
        bool present = (r != ~0ull);
        unsigned tok = (unsigned)r;                       // low 32
        float score  = __uint_as_float(~(unsigned)(r >> 32));
        out[t]       = present ? (float)tok : 0.0f;
        out[MSL + t] = present ? score : NEGF;
    }
}

extern "C" void kernel_launch(void* const* d_in, const int* in_sizes, int n_in,
                              void* d_out, int out_size)
{
    const int*   toks_in  = (const int*)  d_in[0];
    const int*   toks_mem = (const int*)  d_in[1];
    const float* emb      = (const float*)d_in[2];
    const float* w1       = (const float*)d_in[3];
    const float* b1       = (const float*)d_in[4];
    const float* w2       = (const float*)d_in[5];
    const float* b2       = (const float*)d_in[6];
    const int n_toks = in_sizes[0];

    gemv_kernel<<<MSL * NSLAB, 256>>>(toks_in, n_toks, toks_mem, emb, w1);
    reduce_kernel<<<128, 256>>>(b1);
    final_kernel<<<1, 256>>>(toks_in, n_toks, toks_mem, w2, b2, (float*)d_out);
}

// round 9
// speedup vs baseline: 1.1981x; 1.1981x over previous
#include <cuda_runtime.h>
#include <cuda_bf16.h>
#include <cstdint>

#define MSL 256
#define EMB 1024
#define NHID 64
#define NSLAB 4
#define DSLAB (EMB / NSLAB)   // 256
#define NEGF (-1e20f)

// Transposed scratch for coalesced reduction: [in/mem][slab][k][pos]
__device__ float g_part[2][NSLAB][NHID][MSL];
// Reduced + ReLU'd hidden vectors. [in/mem][k]
__device__ float g_h[2][NHID];

// ---------------------------------------------------------------------------
// Kernel A (unchanged from the 22.0us R3 best): fused dual GEMV over w1.
// grid = 1024 (pos = b>>2, slab = b&3), block = 256 threads, 32 regs.
// ---------------------------------------------------------------------------
__global__ __launch_bounds__(256) void gemv_kernel(
    const int* __restrict__ toks_in, int n_toks,
    const int* __restrict__ toks_mem,
    const float* __restrict__ emb,
    const float* __restrict__ w1)
{
    __shared__ float s_in[DSLAB];
    __shared__ float s_mem[DSLAB];
    __shared__ float red_in[16][NHID];
    __shared__ float red_mem[16][NHID];

    const int pos    = blockIdx.x >> 2;
    const int slab   = blockIdx.x & 3;
    const int d_base = slab * DSLAB;
    const int t      = threadIdx.x;

    const int tok_in  = (pos < n_toks) ? toks_in[pos] : 0;  // PAD = 0
    const int tok_mem = toks_mem[pos];

    if (t < 64) {
        ((float4*)s_in)[t] =
            ((const float4*)(emb + (size_t)tok_in * EMB + d_base))[t];
    } else if (t < 128) {
        ((float4*)s_mem)[t - 64] =
            ((const float4*)(emb + (size_t)tok_mem * EMB + d_base))[t - 64];
    }
    __syncthreads();

    const float4* wrow4 =
        (const float4*)(w1 + ((size_t)pos * EMB + d_base) * NHID);
    const int j_off = t >> 4;          // 0..15  (d stripe)
    const int k0    = (t & 15) * 4;    // 0,4,...,60

    float4 ai = make_float4(0.f, 0.f, 0.f, 0.f);
    float4 am = make_float4(0.f, 0.f, 0.f, 0.f);

    #pragma unroll
    for (int d0 = 0; d0 < DSLAB; d0 += 16) {
        float4 w = wrow4[d0 * 16 + t];   // contiguous 4KB across the block
        int   d  = d0 + j_off;
        float a  = s_in[d];
        float b  = s_mem[d];
        ai.x += a * w.x; ai.y += a * w.y; ai.z += a * w.z; ai.w += a * w.w;
        am.x += b * w.x; am.y += b * w.y; am.z += b * w.z; am.w += b * w.w;
    }

    red_in [j_off][k0 + 0] = ai.x;
    red_in [j_off][k0 + 1] = ai.y;
    red_in [j_off][k0 + 2] = ai.z;
    red_in [j_off][k0 + 3] = ai.w;
    red_mem[j_off][k0 + 0] = am.x;
    red_mem[j_off][k0 + 1] = am.y;
    red_mem[j_off][k0 + 2] = am.z;
    red_mem[j_off][k0 + 3] = am.w;
    __syncthreads();

    if (t < NHID) {
        float si = 0.f, sm = 0.f;
        #pragma unroll
        for (int r = 0; r < 16; ++r) {
            si += red_in [r][t];
            sm += red_mem[r][t];
        }
        g_part[0][slab][t][pos] = si;
        g_part[1][slab][t][pos] = sm;
    }
}

// ---------------------------------------------------------------------------
// Kernel B: reduce g_part over (slab, pos) -> +b1 -> ReLU -> g_h.
// grid = 128 (one block per (s,k)), block = 256 (one thread per pos).
// ---------------------------------------------------------------------------
__global__ __launch_bounds__(256) void reduce_kernel(
    const float* __restrict__ b1)
{
    __shared__ float warp_sums[8];
    const int s = blockIdx.x >> 6;     // 0..1
    const int k = blockIdx.x & 63;     // 0..63
    const int t = threadIdx.x;

    float v = g_part[s][0][k][t] + g_part[s][1][k][t]
            + g_part[s][2][k][t] + g_part[s][3][k][t];

    #pragma unroll
    for (int off = 16; off > 0; off >>= 1)
        v += __shfl_down_sync(0xffffffffu, v, off);
    if ((t & 31) == 0) warp_sums[t >> 5] = v;
    __syncthreads();
    if (t == 0) {
        float sum = 0.f;
        #pragma unroll
        for (int w = 0; w < 8; ++w) sum += warp_sums[w];
        g_h[s][k] = fmaxf(sum + b1[k], 0.f);
    }
}

// ---------------------------------------------------------------------------
// Register-resident bitonic sort of 512 u64 keys, 512 threads (one element
// per thread). Stages with j<32 are pure __shfl_xor (no barrier, no SMEM);
// only the 10 stages with j>=32 round-trip through SMEM (2 barriers each).
// Ascending.
// ---------------------------------------------------------------------------
__device__ __forceinline__ void bitonic512_reg(
    unsigned long long& v, unsigned long long* keys)
{
    const int i = threadIdx.x;
    #pragma unroll
    for (int k = 2; k <= 512; k <<= 1) {
        #pragma unroll
        for (int j = k >> 1; j > 0; j >>= 1) {
            unsigned long long o;
            if (j < 32) {
                o = __shfl_xor_sync(0xffffffffu, v, j);
            } else {
                __syncthreads();           // protect prior reads of keys[]
                keys[i] = v;
                __syncthreads();
                o = keys[i ^ j];
            }
            bool keep_min = (((i & j) == 0) == ((i & k) == 0));
            v = keep_min ? (v < o ? v : o) : (v > o ? v : o);
        }
    }
}

// ---------------------------------------------------------------------------
// Kernel C: layer2 + sigmoid -> mask PAD -> dedup (scatter-max) + top-k via
// two register-bitonic sorts -> emit. 1 block, 512 threads (one score and
// one sort element per thread).
// ---------------------------------------------------------------------------
__global__ __launch_bounds__(512) void final_kernel(
    const int* __restrict__ toks_in, int n_toks,
    const int* __restrict__ toks_mem,
    const float* __restrict__ w2,
    const float* __restrict__ b2,
    float* __restrict__ out)
{
    __shared__ float h_sh[2][NHID];
    __shared__ unsigned long long keys[512];

    const int t   = threadIdx.x;
    const int pos = t & 255;
    const int sel = t >> 8;            // 0 = input scores, 1 = memory scores

    // Token for my entry (issue load early).
    int tok = sel ? toks_mem[pos] : ((pos < n_toks) ? toks_in[pos] : 0);

    if (t < 2 * NHID) h_sh[t >> 6][t & 63] = g_h[t >> 6][t & 63];
    __syncthreads();

    // ---- layer 2 + sigmoid: one score per thread, 64 independent loads ----
    float acc = b2[pos];
    {
        const float* hv = h_sh[sel];
        #pragma unroll
        for (int k = 0; k < NHID; ++k)
            acc += hv[k] * w2[k * MSL + pos];   // coalesced; 2nd half L1-hits
    }
    float score = 1.f / (1.f + expf(-acc));

    // ---- key1 = (token asc, score desc); PAD -> sentinel ----
    unsigned sb = __float_as_uint(score);      // positive floats: monotonic
    unsigned long long v = (tok == 0) ? ~0ull
        : (((unsigned long long)(unsigned)tok << 32) | (unsigned)(~sb));

    // Sort1: groups duplicate tokens; best score first within each group.
    bitonic512_reg(v, keys);

    // ---- dedup: winner = first entry of its token run ----
    __syncthreads();
    keys[t] = v;
    __syncthreads();
    unsigned long long prev = (t == 0) ? ~0ull : keys[t - 1];
    bool win = (v != ~0ull) && (t == 0 || (v >> 32) != (prev >> 32));
    __syncthreads();                   // all reads done before sort2 reuses keys

    // key2 = swap halves: (~score_bits)<<32 | token -> asc = score desc, tok asc
    v = win ? ((v << 32) | (v >> 32)) : ~0ull;

    // Sort2: top-k order.
    bitonic512_reg(v, keys);

    // ---- emit first 256 (tokens as float, then scores) ----
    if (t < MSL) {
        bool present = (v != ~0ull);
        unsigned otok = (unsigned)v;                      // low 32
        float oscore  = __uint_as_float(~(unsigned)(v >> 32));
        out[t]       = present ? (float)otok : 0.0f;
        out[MSL + t] = present ? oscore : NEGF;
    }
}

extern "C" void kernel_launch(void* const* d_in, const int* in_sizes, int n_in,
                              void* d_out, int out_size)
{
    const int*   toks_in  = (const int*)  d_in[0];
    const int*   toks_mem = (const int*)  d_in[1];
    const float* emb      = (const float*)d_in[2];
    const float* w1       = (const float*)d_in[3];
    const float* b1       = (const float*)d_in[4];
    const float* w2       = (const float*)d_in[5];
    const float* b2       = (const float*)d_in[6];
    const int n_toks = in_sizes[0];

    gemv_kernel<<<MSL * NSLAB, 256>>>(toks_in, n_toks, toks_mem, emb, w1);
    reduce_kernel<<<128, 256>>>(b1);
    final_kernel<<<1, 512>>>(toks_in, n_toks, toks_mem, w2, b2, (float*)d_out);
}

// round 11
// speedup vs baseline: 1.3310x; 1.1109x over previous
#include <cuda_runtime.h>
#include <cuda_bf16.h>
#include <cstdint>

#define MSL 256
#define EMB 1024
#define NHID 64
#define NSLAB 4
#define DSLAB (EMB / NSLAB)   // 256
#define NEGF (-1e20f)

// Transposed scratch for coalesced reduction: [in/mem][slab][k][pos]
__device__ float g_part[2][NSLAB][NHID][MSL];
// Reduced + ReLU'd hidden vectors. [in/mem][k]
__device__ float g_h[2][NHID];

// ---------------------------------------------------------------------------
// Kernel A (proven): fused dual GEMV over w1.
// grid = 1024 (pos = b>>2, slab = b&3), block = 256 threads, 32 regs.
// Triggers PDL completion after its stores so dependents launch in its tail.
// ---------------------------------------------------------------------------
__global__ __launch_bounds__(256) void gemv_kernel(
    const int* __restrict__ toks_in, int n_toks,
    const int* __restrict__ toks_mem,
    const float* __restrict__ emb,
    const float* __restrict__ w1)
{
    __shared__ float s_in[DSLAB];
    __shared__ float s_mem[DSLAB];
    __shared__ float red_in[16][NHID];
    __shared__ float red_mem[16][NHID];

    const int pos    = blockIdx.x >> 2;
    const int slab   = blockIdx.x & 3;
    const int d_base = slab * DSLAB;
    const int t      = threadIdx.x;

    const int tok_in  = (pos < n_toks) ? toks_in[pos] : 0;  // PAD = 0
    const int tok_mem = toks_mem[pos];

    if (t < 64) {
        ((float4*)s_in)[t] =
            ((const float4*)(emb + (size_t)tok_in * EMB + d_base))[t];
    } else if (t < 128) {
        ((float4*)s_mem)[t - 64] =
            ((const float4*)(emb + (size_t)tok_mem * EMB + d_base))[t - 64];
    }
    __syncthreads();

    const float4* wrow4 =
        (const float4*)(w1 + ((size_t)pos * EMB + d_base) * NHID);
    const int j_off = t >> 4;          // 0..15  (d stripe)
    const int k0    = (t & 15) * 4;    // 0,4,...,60

    float4 ai = make_float4(0.f, 0.f, 0.f, 0.f);
    float4 am = make_float4(0.f, 0.f, 0.f, 0.f);

    #pragma unroll
    for (int d0 = 0; d0 < DSLAB; d0 += 16) {
        float4 w = wrow4[d0 * 16 + t];   // contiguous 4KB across the block
        int   d  = d0 + j_off;
        float a  = s_in[d];
        float b  = s_mem[d];
        ai.x += a * w.x; ai.y += a * w.y; ai.z += a * w.z; ai.w += a * w.w;
        am.x += b * w.x; am.y += b * w.y; am.z += b * w.z; am.w += b * w.w;
    }

    red_in [j_off][k0 + 0] = ai.x;
    red_in [j_off][k0 + 1] = ai.y;
    red_in [j_off][k0 + 2] = ai.z;
    red_in [j_off][k0 + 3] = ai.w;
    red_mem[j_off][k0 + 0] = am.x;
    red_mem[j_off][k0 + 1] = am.y;
    red_mem[j_off][k0 + 2] = am.z;
    red_mem[j_off][k0 + 3] = am.w;
    __syncthreads();

    if (t < NHID) {
        float si = 0.f, sm = 0.f;
        #pragma unroll
        for (int r = 0; r < 16; ++r) {
            si += red_in [r][t];
            sm += red_mem[r][t];
        }
        g_part[0][slab][t][pos] = si;
        g_part[1][slab][t][pos] = sm;
    }

    // Allow the dependent reduce kernel to begin launching (its grid-dep
    // sync still waits for this grid's full completion -> correctness safe).
    cudaTriggerProgrammaticLaunchCompletion();
}

// ---------------------------------------------------------------------------
// Kernel B: reduce g_part over (slab, pos) -> +b1 -> ReLU -> g_h.
// grid = 128 (one block per (s,k)), block = 256 (one thread per pos).
// PDL: prologue (b1 load) runs before the grid-dep sync.
// ---------------------------------------------------------------------------
__global__ __launch_bounds__(256) void reduce_kernel(
    const float* __restrict__ b1)
{
    __shared__ float warp_sums[8];
    const int s = blockIdx.x >> 6;     // 0..1
    const int k = blockIdx.x & 63;     // 0..63
    const int t = threadIdx.x;

    float bias = b1[k];                // independent of upstream

    cudaGridDependencySynchronize();   // wait for gemv grid completion

    float v = g_part[s][0][k][t] + g_part[s][1][k][t]
            + g_part[s][2][k][t] + g_part[s][3][k][t];

    #pragma unroll
    for (int off = 16; off > 0; off >>= 1)
        v += __shfl_down_sync(0xffffffffu, v, off);
    if ((t & 31) == 0) warp_sums[t >> 5] = v;
    __syncthreads();
    if (t == 0) {
        float sum = 0.f;
        #pragma unroll
        for (int w = 0; w < 8; ++w) sum += warp_sums[w];
        g_h[s][k] = fmaxf(sum + bias, 0.f);
    }

    cudaTriggerProgrammaticLaunchCompletion();
}

// ---------------------------------------------------------------------------
// Register-resident bitonic sort of 512 u64 keys, 512 threads (one element
// per thread). j<32 stages are pure __shfl_xor; only j>=32 stages round-trip
// through SMEM. Ascending.
// ---------------------------------------------------------------------------
__device__ __forceinline__ void bitonic512_reg(
    unsigned long long& v, unsigned long long* keys)
{
    const int i = threadIdx.x;
    #pragma unroll
    for (int k = 2; k <= 512; k <<= 1) {
        #pragma unroll
        for (int j = k >> 1; j > 0; j >>= 1) {
            unsigned long long o;
            if (j < 32) {
                o = __shfl_xor_sync(0xffffffffu, v, j);
            } else {
                __syncthreads();           // protect prior reads of keys[]
                keys[i] = v;
                __syncthreads();
                o = keys[i ^ j];
            }
            bool keep_min = (((i & j) == 0) == ((i & k) == 0));
            v = keep_min ? (v < o ? v : o) : (v > o ? v : o);
        }
    }
}

// ---------------------------------------------------------------------------
// Kernel C: layer2 + sigmoid -> PAD mask -> dedup + top-k via two
// register-bitonic sorts -> emit. 1 block, 512 threads.
// PDL: prologue preloads tokens, b2, and the full w2 column into registers
// before the grid-dep sync (overlaps with reduce execution).
// ---------------------------------------------------------------------------
__global__ __launch_bounds__(512) void final_kernel(
    const int* __restrict__ toks_in, int n_toks,
    const int* __restrict__ toks_mem,
    const float* __restrict__ w2,
    const float* __restrict__ b2,
    float* __restrict__ out)
{
    __shared__ float h_sh[2][NHID];
    __shared__ unsigned long long keys[512];

    const int t   = threadIdx.x;
    const int pos = t & 255;
    const int sel = t >> 8;            // 0 = input scores, 1 = memory scores

    // ---- prologue: everything independent of g_h ----
    int   tok  = sel ? toks_mem[pos] : ((pos < n_toks) ? toks_in[pos] : 0);
    float bias = b2[pos];
    float w2v[NHID];
    #pragma unroll
    for (int k = 0; k < NHID; ++k)
        w2v[k] = w2[k * MSL + pos];    // coalesced; 2nd half L1-hits

    cudaGridDependencySynchronize();   // wait for reduce grid completion

    if (t < 2 * NHID) h_sh[t >> 6][t & 63] = g_h[t >> 6][t & 63];
    __syncthreads();

    // ---- layer 2 + sigmoid: one score per thread ----
    float acc = bias;
    {
        const float* hv = h_sh[sel];
        #pragma unroll
        for (int k = 0; k < NHID; ++k)
            acc += hv[k] * w2v[k];
    }
    float score = 1.f / (1.f + expf(-acc));

    // ---- key1 = (token asc, score desc); PAD -> sentinel ----
    unsigned sb = __float_as_uint(score);      // positive floats: monotonic
    unsigned long long v = (tok == 0) ? ~0ull
        : (((unsigned long long)(unsigned)tok << 32) | (unsigned)(~sb));

    // Sort1: groups duplicate tokens; best score first within each group.
    bitonic512_reg(v, keys);

    // ---- dedup: winner = first entry of its token run ----
    __syncthreads();
    keys[t] = v;
    __syncthreads();
    unsigned long long prev = (t == 0) ? ~0ull : keys[t - 1];
    bool win = (v != ~0ull) && (t == 0 || (v >> 32) != (prev >> 32));
    __syncthreads();                   // all reads done before sort2 reuses keys

    // key2 = swap halves: (~score_bits)<<32 | token -> asc = score desc, tok asc
    v = win ? ((v << 32) | (v >> 32)) : ~0ull;

    // Sort2: top-k order.
    bitonic512_reg(v, keys);

    // ---- emit first 256 (tokens as float, then scores) ----
    if (t < MSL) {
        bool present = (v != ~0ull);
        unsigned otok = (unsigned)v;                      // low 32
        float oscore  = __uint_as_float(~(unsigned)(v >> 32));
        out[t]       = present ? (float)otok : 0.0f;
        out[MSL + t] = present ? oscore : NEGF;
    }
}

extern "C" void kernel_launch(void* const* d_in, const int* in_sizes, int n_in,
                              void* d_out, int out_size)
{
    const int*   toks_in  = (const int*)  d_in[0];
    const int*   toks_mem = (const int*)  d_in[1];
    const float* emb      = (const float*)d_in[2];
    const float* w1       = (const float*)d_in[3];
    const float* b1       = (const float*)d_in[4];
    const float* w2       = (const float*)d_in[5];
    const float* b2       = (const float*)d_in[6];
    const int n_toks = in_sizes[0];

    gemv_kernel<<<MSL * NSLAB, 256>>>(toks_in, n_toks, toks_mem, emb, w1);

    cudaLaunchAttribute pdl[1];
    pdl[0].id = cudaLaunchAttributeProgrammaticStreamSerialization;
    pdl[0].val.programmaticStreamSerializationAllowed = 1;

    {
        cudaLaunchConfig_t cfg = {};
        cfg.gridDim  = dim3(128);
        cfg.blockDim = dim3(256);
        cfg.stream   = 0;
        cfg.attrs    = pdl;
        cfg.numAttrs = 1;
        cudaLaunchKernelEx(&cfg, reduce_kernel, b1);
    }
    {
        cudaLaunchConfig_t cfg = {};
        cfg.gridDim  = dim3(1);
        cfg.blockDim = dim3(512);
        cfg.stream   = 0;
        cfg.attrs    = pdl;
        cfg.numAttrs = 1;
        cudaLaunchKernelEx(&cfg, final_kernel, toks_in, n_toks, toks_mem,
                           w2, b2, (float*)d_out);
    }
}